// round 13
// baseline (speedup 1.0000x reference)
#include <cuda_runtime.h>
#include <math.h>

#define NN 50000
#define EE 800000
#define GG 64
#define HID 64
#define CC 8
#define NBLK 49     // ceil(NN/1024)
#define G1BLK 3125  // gemm1 blocks: 16 nodes each
#define HBLK 782    // hist blocks: 1024 edges each

// ---- combined zeroed scratch (single memset) --------------------------------
#define OFF_DEG  0
#define OFF_POS  NN
#define OFF_BLK  (2*NN)
#define OFF_CNT  (2*NN + NBLK)
#define OFF_POOL (2*NN + NBLK + GG)
#define INTS_TOTAL (OFF_POOL + GG*CC)
__device__ int g_ints[INTS_TOTAL];

__device__ __align__(256) float g_hf[NN * HID];    // h fp32 (layers 1-2)
__device__ __align__(256) float g_lin3[NN * CC];   // h fp32 (layer 3)
__device__ __align__(256) float g_act[NN * HID];   // post-agg activations
__device__ float g_as[NN];
__device__ float g_ad[NN];
__device__ int   g_off[NN + 1];
__device__ int   g_esrc[EE + NN];
__device__ float g_ew[EE + NN];    // layer-1 edge logits (leakyrelu applied)
__device__ int   g_is64;

// ---------------- index dtype handling (int64 vs int32) ----------------------
__device__ __forceinline__ int ldid(const void* p, long long i, int is64) {
    return is64 ? (int)((const long long*)p)[i] : ((const int*)p)[i];
}
__device__ __forceinline__ int detect64(const void* ei) {
    const int* p = (const int*)ei;
    int ok = 1;
#pragma unroll
    for (int q = 0; q < 64; q++) ok &= (p[2 * q + 1] == 0);
    return ok;
}

// ---------------- packed f32x2 helpers (Blackwell) ----------------------------
__device__ __forceinline__ void ffma2(unsigned long long& acc,
                                      unsigned long long a, unsigned long long b) {
    asm("fma.rn.f32x2 %0, %1, %2, %0;" : "+l"(acc) : "l"(a), "l"(b));
}
__device__ __forceinline__ unsigned long long packf2(float v) {
    unsigned long long r;
    asm("mov.b64 %0, {%1, %1};" : "=l"(r) : "f"(v));
    return r;
}
__device__ __forceinline__ float2 unpackf2(unsigned long long v) {
    float2 r;
    asm("mov.b64 {%0, %1}, %2;" : "=f"(r.x), "=f"(r.y) : "l"(v));
    return r;
}

// ---- order-preserving float<->uint keys for REDUX max ------------------------
__device__ __forceinline__ unsigned fkey(float f) {
    unsigned u = __float_as_uint(f);
    return (u & 0x80000000u) ? ~u : (u | 0x80000000u);
}
__device__ __forceinline__ float funkey(unsigned k) {
    unsigned u = (k & 0x80000000u) ? (k ^ 0x80000000u) : ~k;
    return __uint_as_float(u);
}

// ============ k_front: gemm1 (11->64, fused alpha) + hist, disjoint blocks ===
__global__ void k_front(const float* __restrict__ x, const float* __restrict__ W,
                        const float* __restrict__ a_s, const float* __restrict__ a_d,
                        const void* ei) {
    __shared__ float sh[176 + 64];
    __shared__ int sIs64;
    int tid = threadIdx.x;           // 256
    if (blockIdx.x < G1BLK) {
        float* xs = sh;
        float* red = sh + 176;
        int nodeBase16 = blockIdx.x * 16;
        if (tid < 176) xs[tid] = x[(long long)nodeBase16 * 11 + tid];
        __syncthreads();
        int f = tid & 63, grp = tid >> 6;
        float acc[4] = {};
        for (int k = 0; k < 11; k++) {
            float w = W[k * 64 + f];
#pragma unroll
            for (int i = 0; i < 4; i++) acc[i] += xs[(grp * 4 + i) * 11 + k] * w;
        }
        float asf = a_s[f], adf = a_d[f];
        float ps[4], pd[4];
#pragma unroll
        for (int i = 0; i < 4; i++) {
            int n = nodeBase16 + grp * 4 + i;
            g_hf[(long long)n * 64 + f] = acc[i];
            ps[i] = acc[i] * asf; pd[i] = acc[i] * adf;
        }
#pragma unroll
        for (int i = 0; i < 4; i++)
#pragma unroll
            for (int o = 16; o; o >>= 1) {
                ps[i] += __shfl_xor_sync(0xFFFFFFFFu, ps[i], o);
                pd[i] += __shfl_xor_sync(0xFFFFFFFFu, pd[i], o);
            }
        int wb = tid >> 5, lane = tid & 31;
        if (lane == 0)
#pragma unroll
            for (int i = 0; i < 4; i++) {
                red[(wb * 4 + i) * 2 + 0] = ps[i];
                red[(wb * 4 + i) * 2 + 1] = pd[i];
            }
        __syncthreads();
        if ((tid & 63) == 0)
#pragma unroll
            for (int i = 0; i < 4; i++) {
                int n = nodeBase16 + grp * 4 + i;
                g_as[n] = red[((2 * grp) * 4 + i) * 2 + 0] + red[((2 * grp + 1) * 4 + i) * 2 + 0];
                g_ad[n] = red[((2 * grp) * 4 + i) * 2 + 1] + red[((2 * grp + 1) * 4 + i) * 2 + 1];
            }
    } else {
        int hb = blockIdx.x - G1BLK;
        if (tid == 0) {
            sIs64 = detect64(ei);              // once per block, not per thread
            if (hb == 0) g_is64 = sIs64;
        }
        __syncthreads();
        int is64 = sIs64;
        int base = hb * 1024 + tid;
        int d[4];
#pragma unroll
        for (int q = 0; q < 4; q++) {
            int e = base + q * 256;
            d[q] = (e < EE) ? ldid(ei, (long long)EE + e, is64) : -1;
        }
#pragma unroll
        for (int q = 0; q < 4; q++)
            if (d[q] >= 0) atomicAdd(&g_ints[OFF_DEG + d[q]], 1);
    }
}

// ====== single-kernel scan (decoupled lookback) + self-loop placement ========
// also writes layer-1 self-loop logit into g_ew (g_as/g_ad valid after k_front)
__global__ void k_scan() {
    __shared__ int wsum[32];
    __shared__ int prevsum;
    int tid = threadIdx.x, b = blockIdx.x;
    int lane = tid & 31, w = tid >> 5;
    int i = b * 1024 + tid;
    int x0 = (i < NN) ? (g_ints[OFF_DEG + i] + 1) : 0;   // +1 = self loop
    int x = x0;
#pragma unroll
    for (int o = 1; o < 32; o <<= 1) {
        int t = __shfl_up_sync(0xFFFFFFFFu, x, o);
        if (lane >= o) x += t;
    }
    if (lane == 31) wsum[w] = x;
    __syncthreads();
    if (w == 0) {
        int s = wsum[lane];
#pragma unroll
        for (int o = 1; o < 32; o <<= 1) {
            int t = __shfl_up_sync(0xFFFFFFFFu, s, o);
            if (lane >= o) s += t;
        }
        wsum[lane] = s;
    }
    __syncthreads();
    int total = wsum[31];
    int incl = x + (w ? wsum[w - 1] : 0);
    if (tid == 0) atomicExch(&g_ints[OFF_BLK + b], total | 0x40000000);
    if (w == 0) {
        int acc = 0;
        for (int p = lane; p < b; p += 32) {
            int val;
            do { val = *(volatile int*)&g_ints[OFF_BLK + p]; } while (!(val & 0x40000000));
            acc += val & 0x3FFFFFFF;
        }
#pragma unroll
        for (int o = 16; o; o >>= 1) acc += __shfl_xor_sync(0xFFFFFFFFu, acc, o);
        if (lane == 0) prevsum = acc;
    }
    __syncthreads();
    if (i < NN) {
        int inclF = incl + prevsum;
        g_off[i + 1] = inclF;
        int slot = inclF - x0;
        g_esrc[slot] = i;             // self loop occupies first slot
        float t = g_as[i] + g_ad[i];
        g_ew[slot] = t > 0.f ? t : 0.2f * t;
    }
    if (i == 0) g_off[0] = 0;
}

// ============ scatter: 4 edges per thread + layer-1 edge logits ==============
__global__ void k_scatter(const void* ei) {
    int is64 = g_is64;                // set by k_front
    int base = blockIdx.x * 1024 + threadIdx.x;
    int s[4], d[4];
#pragma unroll
    for (int q = 0; q < 4; q++) {
        int e = base + q * 256;
        if (e < EE) {
            s[q] = ldid(ei, e, is64);
            d[q] = ldid(ei, (long long)EE + e, is64);
        } else d[q] = -1;
    }
    float ea[4], eb[4];
#pragma unroll
    for (int q = 0; q < 4; q++) {
        if (d[q] >= 0) { ea[q] = g_as[s[q]]; eb[q] = g_ad[d[q]]; }
    }
#pragma unroll
    for (int q = 0; q < 4; q++) {
        if (d[q] >= 0) {
            int p = g_off[d[q]] + 1 + atomicAdd(&g_ints[OFF_POS + d[q]], 1);
            g_esrc[p] = s[q];
            float t = ea[q] + eb[q];
            g_ew[p] = t > 0.f ? t : 0.2f * t;
        }
    }
}

// ------- GEMM 64 -> 64, register tiled 4x4, fused alpha, fp32 h out ----------
__global__ void k_gemm64(const float* __restrict__ x, const float* __restrict__ W,
                         const float* __restrict__ a_s, const float* __restrict__ a_d) {
    __shared__ float ws[64 * 64];
    __shared__ float xsT[64 * 32];
    int tid = threadIdx.x;   // 128
    int nb = blockIdx.x * 32;
    {
        const float4* W4 = (const float4*)W;
        float4* ws4 = (float4*)ws;
        for (int i = tid; i < 1024; i += 128) ws4[i] = W4[i];
    }
    {
        int n = tid & 31, kc = tid >> 5;
        bool ok = (nb + n) < NN;
        const float4* xr = (const float4*)(x + (long long)(nb + n) * 64 + kc * 16);
#pragma unroll
        for (int q = 0; q < 4; q++) {
            float4 v = ok ? xr[q] : make_float4(0.f, 0.f, 0.f, 0.f);
            int k = kc * 16 + q * 4;
            xsT[(k + 0) * 32 + n] = v.x; xsT[(k + 1) * 32 + n] = v.y;
            xsT[(k + 2) * 32 + n] = v.z; xsT[(k + 3) * 32 + n] = v.w;
        }
    }
    __syncthreads();
    int tf = tid & 15, tn = tid >> 4;
    float acc[4][4] = {};
    for (int k = 0; k < 64; k++) {
        float4 xv = *(const float4*)&xsT[k * 32 + tn * 4];
        float4 wv = *(const float4*)&ws[k * 64 + tf * 4];
        float xa[4] = {xv.x, xv.y, xv.z, xv.w};
        float wa[4] = {wv.x, wv.y, wv.z, wv.w};
#pragma unroll
        for (int i = 0; i < 4; i++)
#pragma unroll
            for (int j = 0; j < 4; j++) acc[i][j] += xa[i] * wa[j];
    }
    float4 as4 = ((const float4*)a_s)[tf];
    float4 ad4 = ((const float4*)a_d)[tf];
    float asA[4] = {as4.x, as4.y, as4.z, as4.w};
    float adA[4] = {ad4.x, ad4.y, ad4.z, ad4.w};
    float ps[4], pd[4];
#pragma unroll
    for (int i = 0; i < 4; i++) {
        int n = nb + tn * 4 + i;
        float s = 0.f, dd = 0.f;
#pragma unroll
        for (int j = 0; j < 4; j++) { s += acc[i][j] * asA[j]; dd += acc[i][j] * adA[j]; }
        ps[i] = s; pd[i] = dd;
        if (n < NN)
            *(float4*)&g_hf[(long long)n * 64 + tf * 4] =
                make_float4(acc[i][0], acc[i][1], acc[i][2], acc[i][3]);
    }
#pragma unroll
    for (int i = 0; i < 4; i++)
#pragma unroll
        for (int o = 8; o; o >>= 1) {
            ps[i] += __shfl_xor_sync(0xFFFFFFFFu, ps[i], o);
            pd[i] += __shfl_xor_sync(0xFFFFFFFFu, pd[i], o);
        }
    if (tf == 0)
#pragma unroll
        for (int i = 0; i < 4; i++) {
            int n = nb + tn * 4 + i;
            if (n < NN) { g_as[n] = ps[i]; g_ad[n] = pd[i]; }
        }
}

// ---------------- GEMM layer3: 64 -> 8, fused alpha, fp32 out ----------------
__global__ void k_gemm3(const float* __restrict__ x, const float* __restrict__ W,
                        const float* __restrict__ a_s, const float* __restrict__ a_d) {
    const int FI = 64, FO = 8, NPT = 4, NPB = 32;
    __shared__ float xs[NPB * FI];
    int tid = threadIdx.x;   // 64
    int nodeBase = blockIdx.x * NPB;
    for (int i = tid; i < NPB * FI; i += 64) {
        int n = nodeBase + i / FI;
        xs[i] = (n < NN) ? x[(long long)n * FI + (i % FI)] : 0.f;
    }
    __syncthreads();
    int gq = tid / FO, f = tid % FO;
    float acc[NPT] = {};
    for (int k = 0; k < FI; k++) {
        float w = W[k * FO + f];
#pragma unroll
        for (int i = 0; i < NPT; i++) acc[i] += xs[(gq * NPT + i) * FI + k] * w;
    }
    float asf = a_s[f], adf = a_d[f];
    float ps[NPT], pd[NPT];
#pragma unroll
    for (int i = 0; i < NPT; i++) {
        int n = nodeBase + gq * NPT + i;
        if (n < NN) g_lin3[(long long)n * FO + f] = acc[i];
        ps[i] = acc[i] * asf; pd[i] = acc[i] * adf;
    }
#pragma unroll
    for (int i = 0; i < NPT; i++)
#pragma unroll
        for (int o = 4; o; o >>= 1) {
            ps[i] += __shfl_xor_sync(0xFFFFFFFFu, ps[i], o);
            pd[i] += __shfl_xor_sync(0xFFFFFFFFu, pd[i], o);
        }
    if (f == 0)
#pragma unroll
        for (int i = 0; i < NPT; i++) {
            int n = nodeBase + gq * NPT + i;
            if (n < NN) { g_as[n] = ps[i]; g_ad[n] = pd[i]; }
        }
}

// ---- layer-1 agg: softmax over PRECOMPUTED edge logits (coalesced reads) ----
__global__ void k_agg64ew(const float* __restrict__ bias, float* __restrict__ out) {
    __shared__ int2 ssw[8][64];      // (src, weight) staged per warp
    int wl = threadIdx.x >> 5;
    int node = (blockIdx.x << 3) + wl;
    int lane = threadIdx.x & 31;
    if (node >= NN) return;
    int beg = g_off[node], end = g_off[node + 1];

    int s0 = 0, s1 = 0;
    float e0 = -1e30f, e1 = -1e30f;
    int j0 = beg + lane, j1 = beg + 32 + lane;
    if (j0 < end) { s0 = g_esrc[j0]; e0 = g_ew[j0]; }
    if (j1 < end) { s1 = g_esrc[j1]; e1 = g_ew[j1]; }
    float mloc = fmaxf(e0, e1);
    for (int j = beg + 64 + lane; j < end; j += 32)    // rare tail
        mloc = fmaxf(mloc, g_ew[j]);
    float m = funkey(__reduce_max_sync(0xFFFFFFFFu, fkey(mloc)));

    float w0 = (j0 < end) ? __expf(e0 - m) : 0.f;
    float w1 = (j1 < end) ? __expf(e1 - m) : 0.f;
    float den = w0 + w1;
    for (int j = beg + 64 + lane; j < end; j += 32)
        den += __expf(g_ew[j] - m);
#pragma unroll
    for (int o = 16; o; o >>= 1) den += __shfl_xor_sync(0xFFFFFFFFu, den, o);
    float inv = 1.f / den;
    w0 *= inv; w1 *= inv;

    if (j0 < end) ssw[wl][lane]      = make_int2(s0, __float_as_int(w0));
    if (j1 < end) ssw[wl][32 + lane] = make_int2(s1, __float_as_int(w1));
    __syncwarp();

    unsigned long long acc = 0ull;   // feats 2lane, 2lane+1
    int dc = end - beg; if (dc > 64) dc = 64;
#pragma unroll 4
    for (int jj = 0; jj < dc; jj++) {
        int2 p = ssw[wl][jj];
        unsigned long long w2 = packf2(__int_as_float(p.y));
        const unsigned long long* row = (const unsigned long long*)(g_hf + (long long)p.x * 64);
        ffma2(acc, row[lane], w2);
    }
    for (int j = beg + 64; j < end; j++) {   // rare tail (uniform)
        int s = g_esrc[j];
        unsigned long long w2 = packf2(__expf(g_ew[j] - m) * inv);
        const unsigned long long* row = (const unsigned long long*)(g_hf + (long long)s * 64);
        ffma2(acc, row[lane], w2);
    }

    float2 a = unpackf2(acc);
    float2 bb = ((const float2*)bias)[lane];
    float2 r;
    r.x = fmaxf(a.x + bb.x, 0.f);
    r.y = fmaxf(a.y + bb.y, 0.f);
    ((float2*)out)[node * 32 + lane] = r;
}

// -------- layer-2 agg: warp-per-dst softmax + aggregation (exact R8) ---------
__global__ void k_agg64(const float* __restrict__ bias, float* __restrict__ out) {
    __shared__ int2 ssw[8][64];      // (src, weight) staged per warp
    int wl = threadIdx.x >> 5;
    int node = (blockIdx.x << 3) + wl;
    int lane = threadIdx.x & 31;
    if (node >= NN) return;
    int beg = g_off[node], end = g_off[node + 1];
    float adn = g_ad[node];

    int s0 = 0, s1 = 0;
    float e0 = -1e30f, e1 = -1e30f;
    int j0 = beg + lane, j1 = beg + 32 + lane;
    if (j0 < end) { s0 = g_esrc[j0]; float t = g_as[s0] + adn; e0 = t > 0.f ? t : 0.2f * t; }
    if (j1 < end) { s1 = g_esrc[j1]; float t = g_as[s1] + adn; e1 = t > 0.f ? t : 0.2f * t; }
    float mloc = fmaxf(e0, e1);
    for (int j = beg + 64 + lane; j < end; j += 32) {   // rare tail
        int s = g_esrc[j]; float t = g_as[s] + adn; t = t > 0.f ? t : 0.2f * t;
        mloc = fmaxf(mloc, t);
    }
    float m = funkey(__reduce_max_sync(0xFFFFFFFFu, fkey(mloc)));

    float w0 = (j0 < end) ? __expf(e0 - m) : 0.f;
    float w1 = (j1 < end) ? __expf(e1 - m) : 0.f;
    float den = w0 + w1;
    for (int j = beg + 64 + lane; j < end; j += 32) {
        int s = g_esrc[j]; float t = g_as[s] + adn; t = t > 0.f ? t : 0.2f * t;
        den += __expf(t - m);
    }
#pragma unroll
    for (int o = 16; o; o >>= 1) den += __shfl_xor_sync(0xFFFFFFFFu, den, o);
    float inv = 1.f / den;
    w0 *= inv; w1 *= inv;

    if (j0 < end) ssw[wl][lane]      = make_int2(s0, __float_as_int(w0));
    if (j1 < end) ssw[wl][32 + lane] = make_int2(s1, __float_as_int(w1));
    __syncwarp();

    unsigned long long acc = 0ull;   // feats 2lane, 2lane+1
    int dc = end - beg; if (dc > 64) dc = 64;
#pragma unroll 4
    for (int jj = 0; jj < dc; jj++) {
        int2 p = ssw[wl][jj];
        unsigned long long w2 = packf2(__int_as_float(p.y));
        const unsigned long long* row = (const unsigned long long*)(g_hf + (long long)p.x * 64);
        ffma2(acc, row[lane], w2);
    }
    for (int j = beg + 64; j < end; j++) {   // rare tail (uniform)
        int s = g_esrc[j];
        float t = g_as[s] + adn; t = t > 0.f ? t : 0.2f * t;
        unsigned long long w2 = packf2(__expf(t - m) * inv);
        const unsigned long long* row = (const unsigned long long*)(g_hf + (long long)s * 64);
        ffma2(acc, row[lane], w2);
    }

    float2 a = unpackf2(acc);
    float2 bb = ((const float2*)bias)[lane];
    float2 r;
    r.x = fmaxf(a.x + bb.x, 0.f);
    r.y = fmaxf(a.y + bb.y, 0.f);
    ((float2*)out)[node * 32 + lane] = r;
}

// layer-3 agg (F=8): quarter-warp per edge, fused mean-pool accumulation ------
__global__ void k_agg8(const float* __restrict__ bias, const void* batch) {
    __shared__ int2 ssw[8][64];
    int wl = threadIdx.x >> 5;
    int node = (blockIdx.x << 3) + wl;
    int lane = threadIdx.x & 31;
    if (node >= NN) return;
    int beg = g_off[node], end = g_off[node + 1];
    float adn = g_ad[node];

    int s0 = 0, s1 = 0;
    float e0 = -1e30f, e1 = -1e30f;
    int j0 = beg + lane, j1 = beg + 32 + lane;
    if (j0 < end) { s0 = g_esrc[j0]; float t = g_as[s0] + adn; e0 = t > 0.f ? t : 0.2f * t; }
    if (j1 < end) { s1 = g_esrc[j1]; float t = g_as[s1] + adn; e1 = t > 0.f ? t : 0.2f * t; }
    float mloc = fmaxf(e0, e1);
    for (int j = beg + 64 + lane; j < end; j += 32) {
        int s = g_esrc[j]; float t = g_as[s] + adn; t = t > 0.f ? t : 0.2f * t;
        mloc = fmaxf(mloc, t);
    }
    float m = funkey(__reduce_max_sync(0xFFFFFFFFu, fkey(mloc)));

    float w0 = (j0 < end) ? __expf(e0 - m) : 0.f;
    float w1 = (j1 < end) ? __expf(e1 - m) : 0.f;
    float den = w0 + w1;
    for (int j = beg + 64 + lane; j < end; j += 32) {
        int s = g_esrc[j]; float t = g_as[s] + adn; t = t > 0.f ? t : 0.2f * t;
        den += __expf(t - m);
    }
#pragma unroll
    for (int o = 16; o; o >>= 1) den += __shfl_xor_sync(0xFFFFFFFFu, den, o);
    float inv = 1.f / den;
    w0 *= inv; w1 *= inv;

    int dc = end - beg; if (dc > 64) dc = 64;
    int dpad = (dc + 7) & ~7;
    if (dpad > 64) dpad = 64;
    if (j0 < end) ssw[wl][lane]      = make_int2(s0, __float_as_int(w0));
    if (j1 < end) ssw[wl][32 + lane] = make_int2(s1, __float_as_int(w1));
    if (lane < 8 && dc + lane < dpad) ssw[wl][dc + lane] = make_int2(0, 0);
    __syncwarp();

    // quarter-warp per edge: group g = lane>>2 handles edges jj+g, 8 at a time
    int g = lane >> 2, sub = lane & 3;
    unsigned long long acc = 0ull;   // feats 2sub, 2sub+1
    for (int jj = g; jj < dpad; jj += 8) {
        int2 p = ssw[wl][jj];
        unsigned long long w2 = packf2(__int_as_float(p.y));
        unsigned long long v = ((const unsigned long long*)(g_lin3 + (long long)p.x * CC))[sub];
        ffma2(acc, v, w2);
    }
    for (int j = beg + 64 + g; j < end; j += 8) {  // rare tail
        int s = g_esrc[j];
        float t = g_as[s] + adn; t = t > 0.f ? t : 0.2f * t;
        unsigned long long w2 = packf2(__expf(t - m) * inv);
        unsigned long long v = ((const unsigned long long*)(g_lin3 + (long long)s * CC))[sub];
        ffma2(acc, v, w2);
    }

    float2 a = unpackf2(acc);
#pragma unroll
    for (int o = 4; o <= 16; o <<= 1) {
        a.x += __shfl_xor_sync(0xFFFFFFFFu, a.x, o);
        a.y += __shfl_xor_sync(0xFFFFFFFFu, a.y, o);
    }

    int b = ldid(batch, node, g_is64);
    float* pool = (float*)&g_ints[OFF_POOL];
    if (lane < 4) {
        float2 bb = ((const float2*)bias)[lane];
        atomicAdd(&pool[b * CC + 2 * lane],     fmaxf(a.x + bb.x, 0.f));
        atomicAdd(&pool[b * CC + 2 * lane + 1], fmaxf(a.y + bb.y, 0.f));
    }
    if (lane == 0) atomicAdd(&g_ints[OFF_CNT + b], 1);
}

// ---------------- final mean + sigmoid ---------------------------------------
__global__ void k_fin(float* __restrict__ out) {
    int i = blockIdx.x * blockDim.x + threadIdx.x;
    if (i >= GG * CC) return;
    int g = i / CC;
    float c = fmaxf((float)g_ints[OFF_CNT + g], 1.f);
    float v = ((float*)&g_ints[OFF_POOL])[i] / c;
    out[i] = 1.f / (1.f + __expf(-v));
}

// -----------------------------------------------------------------------------
extern "C" void kernel_launch(void* const* d_in, const int* in_sizes, int n_in,
                              void* d_out, int out_size) {
    const float* x     = (const float*)d_in[0];
    const void*  ei    = d_in[1];
    const void*  batch = d_in[3];
    const float* W1  = (const float*)d_in[4];
    const float* a1s = (const float*)d_in[5];
    const float* a1d = (const float*)d_in[6];
    const float* b1  = (const float*)d_in[7];
    const float* W2  = (const float*)d_in[8];
    const float* a2s = (const float*)d_in[9];
    const float* a2d = (const float*)d_in[10];
    const float* b2  = (const float*)d_in[11];
    const float* W3  = (const float*)d_in[12];
    const float* a3s = (const float*)d_in[13];
    const float* a3d = (const float*)d_in[14];
    const float* b3  = (const float*)d_in[15];
    float* out = (float*)d_out;

    float* act;
    void* ints;
    cudaGetSymbolAddress((void**)&act, g_act);
    cudaGetSymbolAddress(&ints, g_ints);

    cudaMemsetAsync(ints, 0, INTS_TOTAL * sizeof(int), 0);

    // CSR build (+ layer-1 edge logits)
    k_front<<<G1BLK + HBLK, 256>>>(x, W1, a1s, a1d, ei);
    k_scan<<<NBLK, 1024>>>();
    k_scatter<<<HBLK, 256>>>(ei);

    // layer-1 aggregation with precomputed logits (ncu-profiled launch)
    k_agg64ew<<<(NN + 7) / 8, 256>>>(b1, act);

    // Layer 2: 64 -> 64
    k_gemm64<<<(NN + 31) / 32, 128>>>(act, W2, a2s, a2d);
    k_agg64<<<(NN + 7) / 8, 256>>>(b2, act);

    // Layer 3: 64 -> 8
    k_gemm3<<<(NN + 31) / 32, 64>>>(act, W3, a3s, a3d);
    k_agg8<<<(NN + 7) / 8, 256>>>(b3, batch);

    // mean + sigmoid
    k_fin<<<2, 256>>>(out);
}

// round 16
// speedup vs baseline: 1.1153x; 1.1153x over previous
#include <cuda_runtime.h>
#include <math.h>

#define NN 50000
#define EE 800000
#define GG 64
#define HID 64
#define CC 8
#define NBLK 49     // ceil(NN/1024)
#define G1BLK 3125  // gemm1 blocks: 16 nodes each
#define HBLK 782    // hist blocks: 1024 edges each
#define AGGBLK 1184 // persistent agg grid: 8 blocks/SM * 148 SMs

// ---- combined zeroed scratch (single memset) --------------------------------
#define OFF_DEG  0
#define OFF_POS  NN
#define OFF_BLK  (2*NN)
#define OFF_CNT  (2*NN + NBLK)
#define OFF_POOL (2*NN + NBLK + GG)
#define INTS_TOTAL (OFF_POOL + GG*CC)
__device__ int g_ints[INTS_TOTAL];

__device__ __align__(256) float g_hf[NN * HID];    // h fp32 (layers 1-2)
__device__ __align__(256) float g_lin3[NN * CC];   // h fp32 (layer 3)
__device__ __align__(256) float g_act[NN * HID];   // post-agg activations
__device__ float g_as[NN];
__device__ float g_ad[NN];
__device__ int   g_off[NN + 1];
__device__ int   g_esrc[EE + NN];
__device__ int   g_is64;

// ---------------- index dtype handling (int64 vs int32) ----------------------
__device__ __forceinline__ int ldid(const void* p, long long i, int is64) {
    return is64 ? (int)((const long long*)p)[i] : ((const int*)p)[i];
}
__device__ __forceinline__ int detect64(const void* ei) {
    const int* p = (const int*)ei;
    int ok = 1;
#pragma unroll
    for (int q = 0; q < 64; q++) ok &= (p[2 * q + 1] == 0);
    return ok;
}

// ---------------- packed f32x2 helpers (Blackwell) ----------------------------
__device__ __forceinline__ void ffma2(unsigned long long& acc,
                                      unsigned long long a, unsigned long long b) {
    asm("fma.rn.f32x2 %0, %1, %2, %0;" : "+l"(acc) : "l"(a), "l"(b));
}
__device__ __forceinline__ unsigned long long packf2(float v) {
    unsigned long long r;
    asm("mov.b64 %0, {%1, %1};" : "=l"(r) : "f"(v));
    return r;
}
__device__ __forceinline__ float2 unpackf2(unsigned long long v) {
    float2 r;
    asm("mov.b64 {%0, %1}, %2;" : "=f"(r.x), "=f"(r.y) : "l"(v));
    return r;
}

// ---- order-preserving float<->uint keys for REDUX max ------------------------
__device__ __forceinline__ unsigned fkey(float f) {
    unsigned u = __float_as_uint(f);
    return (u & 0x80000000u) ? ~u : (u | 0x80000000u);
}
__device__ __forceinline__ float funkey(unsigned k) {
    unsigned u = (k & 0x80000000u) ? (k ^ 0x80000000u) : ~k;
    return __uint_as_float(u);
}

// ============ k_front: gemm1 (11->64, fused alpha) + hist, disjoint blocks ===
__global__ void k_front(const float* __restrict__ x, const float* __restrict__ W,
                        const float* __restrict__ a_s, const float* __restrict__ a_d,
                        const void* ei) {
    __shared__ float sh[176 + 64];
    __shared__ int sIs64;
    int tid = threadIdx.x;           // 256
    if (blockIdx.x < G1BLK) {
        float* xs = sh;
        float* red = sh + 176;
        int nodeBase16 = blockIdx.x * 16;
        if (tid < 176) xs[tid] = x[(long long)nodeBase16 * 11 + tid];
        __syncthreads();
        int f = tid & 63, grp = tid >> 6;
        float acc[4] = {};
        for (int k = 0; k < 11; k++) {
            float w = W[k * 64 + f];
#pragma unroll
            for (int i = 0; i < 4; i++) acc[i] += xs[(grp * 4 + i) * 11 + k] * w;
        }
        float asf = a_s[f], adf = a_d[f];
        float ps[4], pd[4];
#pragma unroll
        for (int i = 0; i < 4; i++) {
            int n = nodeBase16 + grp * 4 + i;
            g_hf[(long long)n * 64 + f] = acc[i];
            ps[i] = acc[i] * asf; pd[i] = acc[i] * adf;
        }
#pragma unroll
        for (int i = 0; i < 4; i++)
#pragma unroll
            for (int o = 16; o; o >>= 1) {
                ps[i] += __shfl_xor_sync(0xFFFFFFFFu, ps[i], o);
                pd[i] += __shfl_xor_sync(0xFFFFFFFFu, pd[i], o);
            }
        int wb = tid >> 5, lane = tid & 31;
        if (lane == 0)
#pragma unroll
            for (int i = 0; i < 4; i++) {
                red[(wb * 4 + i) * 2 + 0] = ps[i];
                red[(wb * 4 + i) * 2 + 1] = pd[i];
            }
        __syncthreads();
        if ((tid & 63) == 0)
#pragma unroll
            for (int i = 0; i < 4; i++) {
                int n = nodeBase16 + grp * 4 + i;
                g_as[n] = red[((2 * grp) * 4 + i) * 2 + 0] + red[((2 * grp + 1) * 4 + i) * 2 + 0];
                g_ad[n] = red[((2 * grp) * 4 + i) * 2 + 1] + red[((2 * grp + 1) * 4 + i) * 2 + 1];
            }
    } else {
        int hb = blockIdx.x - G1BLK;
        if (tid == 0) {
            sIs64 = detect64(ei);              // once per block, not per thread
            if (hb == 0) g_is64 = sIs64;
        }
        __syncthreads();
        int is64 = sIs64;
        int base = hb * 1024 + tid;
        int d[4];
#pragma unroll
        for (int q = 0; q < 4; q++) {
            int e = base + q * 256;
            d[q] = (e < EE) ? ldid(ei, (long long)EE + e, is64) : -1;
        }
#pragma unroll
        for (int q = 0; q < 4; q++)
            if (d[q] >= 0) atomicAdd(&g_ints[OFF_DEG + d[q]], 1);
    }
}

// ====== single-kernel scan (decoupled lookback) + self-loop placement ========
__global__ void k_scan() {
    __shared__ int wsum[32];
    __shared__ int prevsum;
    int tid = threadIdx.x, b = blockIdx.x;
    int lane = tid & 31, w = tid >> 5;
    int i = b * 1024 + tid;
    int x0 = (i < NN) ? (g_ints[OFF_DEG + i] + 1) : 0;   // +1 = self loop
    int x = x0;
#pragma unroll
    for (int o = 1; o < 32; o <<= 1) {
        int t = __shfl_up_sync(0xFFFFFFFFu, x, o);
        if (lane >= o) x += t;
    }
    if (lane == 31) wsum[w] = x;
    __syncthreads();
    if (w == 0) {
        int s = wsum[lane];
#pragma unroll
        for (int o = 1; o < 32; o <<= 1) {
            int t = __shfl_up_sync(0xFFFFFFFFu, s, o);
            if (lane >= o) s += t;
        }
        wsum[lane] = s;
    }
    __syncthreads();
    int total = wsum[31];
    int incl = x + (w ? wsum[w - 1] : 0);
    if (tid == 0) atomicExch(&g_ints[OFF_BLK + b], total | 0x40000000);
    if (w == 0) {
        int acc = 0;
        for (int p = lane; p < b; p += 32) {
            int val;
            do { val = *(volatile int*)&g_ints[OFF_BLK + p]; } while (!(val & 0x40000000));
            acc += val & 0x3FFFFFFF;
        }
#pragma unroll
        for (int o = 16; o; o >>= 1) acc += __shfl_xor_sync(0xFFFFFFFFu, acc, o);
        if (lane == 0) prevsum = acc;
    }
    __syncthreads();
    if (i < NN) {
        int inclF = incl + prevsum;
        g_off[i + 1] = inclF;
        g_esrc[inclF - x0] = i;       // self loop occupies first slot
    }
    if (i == 0) g_off[0] = 0;
}

// ============ scatter: 4 edges per thread ====================================
__global__ void k_scatter(const void* ei) {
    int is64 = g_is64;                // set by k_front
    int base = blockIdx.x * 1024 + threadIdx.x;
    int s[4], d[4];
#pragma unroll
    for (int q = 0; q < 4; q++) {
        int e = base + q * 256;
        if (e < EE) {
            s[q] = ldid(ei, e, is64);
            d[q] = ldid(ei, (long long)EE + e, is64);
        } else d[q] = -1;
    }
#pragma unroll
    for (int q = 0; q < 4; q++) {
        if (d[q] >= 0) {
            int p = g_off[d[q]] + 1 + atomicAdd(&g_ints[OFF_POS + d[q]], 1);
            g_esrc[p] = s[q];
        }
    }
}

// ------- GEMM 64 -> 64, register tiled 4x4, fused alpha, fp32 h out ----------
__global__ void k_gemm64(const float* __restrict__ x, const float* __restrict__ W,
                         const float* __restrict__ a_s, const float* __restrict__ a_d) {
    __shared__ float ws[64 * 64];
    __shared__ float xsT[64 * 32];
    int tid = threadIdx.x;   // 128
    int nb = blockIdx.x * 32;
    {
        const float4* W4 = (const float4*)W;
        float4* ws4 = (float4*)ws;
        for (int i = tid; i < 1024; i += 128) ws4[i] = W4[i];
    }
    {
        int n = tid & 31, kc = tid >> 5;
        bool ok = (nb + n) < NN;
        const float4* xr = (const float4*)(x + (long long)(nb + n) * 64 + kc * 16);
#pragma unroll
        for (int q = 0; q < 4; q++) {
            float4 v = ok ? xr[q] : make_float4(0.f, 0.f, 0.f, 0.f);
            int k = kc * 16 + q * 4;
            xsT[(k + 0) * 32 + n] = v.x; xsT[(k + 1) * 32 + n] = v.y;
            xsT[(k + 2) * 32 + n] = v.z; xsT[(k + 3) * 32 + n] = v.w;
        }
    }
    __syncthreads();
    int tf = tid & 15, tn = tid >> 4;
    float acc[4][4] = {};
    for (int k = 0; k < 64; k++) {
        float4 xv = *(const float4*)&xsT[k * 32 + tn * 4];
        float4 wv = *(const float4*)&ws[k * 64 + tf * 4];
        float xa[4] = {xv.x, xv.y, xv.z, xv.w};
        float wa[4] = {wv.x, wv.y, wv.z, wv.w};
#pragma unroll
        for (int i = 0; i < 4; i++)
#pragma unroll
            for (int j = 0; j < 4; j++) acc[i][j] += xa[i] * wa[j];
    }
    float4 as4 = ((const float4*)a_s)[tf];
    float4 ad4 = ((const float4*)a_d)[tf];
    float asA[4] = {as4.x, as4.y, as4.z, as4.w};
    float adA[4] = {ad4.x, ad4.y, ad4.z, ad4.w};
    float ps[4], pd[4];
#pragma unroll
    for (int i = 0; i < 4; i++) {
        int n = nb + tn * 4 + i;
        float s = 0.f, dd = 0.f;
#pragma unroll
        for (int j = 0; j < 4; j++) { s += acc[i][j] * asA[j]; dd += acc[i][j] * adA[j]; }
        ps[i] = s; pd[i] = dd;
        if (n < NN)
            *(float4*)&g_hf[(long long)n * 64 + tf * 4] =
                make_float4(acc[i][0], acc[i][1], acc[i][2], acc[i][3]);
    }
#pragma unroll
    for (int i = 0; i < 4; i++)
#pragma unroll
        for (int o = 8; o; o >>= 1) {
            ps[i] += __shfl_xor_sync(0xFFFFFFFFu, ps[i], o);
            pd[i] += __shfl_xor_sync(0xFFFFFFFFu, pd[i], o);
        }
    if (tf == 0)
#pragma unroll
        for (int i = 0; i < 4; i++) {
            int n = nb + tn * 4 + i;
            if (n < NN) { g_as[n] = ps[i]; g_ad[n] = pd[i]; }
        }
}

// ---------------- GEMM layer3: 64 -> 8, fused alpha, fp32 out ----------------
__global__ void k_gemm3(const float* __restrict__ x, const float* __restrict__ W,
                        const float* __restrict__ a_s, const float* __restrict__ a_d) {
    const int FI = 64, FO = 8, NPT = 4, NPB = 32;
    __shared__ float xs[NPB * FI];
    int tid = threadIdx.x;   // 64
    int nodeBase = blockIdx.x * NPB;
    for (int i = tid; i < NPB * FI; i += 64) {
        int n = nodeBase + i / FI;
        xs[i] = (n < NN) ? x[(long long)n * FI + (i % FI)] : 0.f;
    }
    __syncthreads();
    int gq = tid / FO, f = tid % FO;
    float acc[NPT] = {};
    for (int k = 0; k < FI; k++) {
        float w = W[k * FO + f];
#pragma unroll
        for (int i = 0; i < NPT; i++) acc[i] += xs[(gq * NPT + i) * FI + k] * w;
    }
    float asf = a_s[f], adf = a_d[f];
    float ps[NPT], pd[NPT];
#pragma unroll
    for (int i = 0; i < NPT; i++) {
        int n = nodeBase + gq * NPT + i;
        if (n < NN) g_lin3[(long long)n * FO + f] = acc[i];
        ps[i] = acc[i] * asf; pd[i] = acc[i] * adf;
    }
#pragma unroll
    for (int i = 0; i < NPT; i++)
#pragma unroll
        for (int o = 4; o; o >>= 1) {
            ps[i] += __shfl_xor_sync(0xFFFFFFFFu, ps[i], o);
            pd[i] += __shfl_xor_sync(0xFFFFFFFFu, pd[i], o);
        }
    if (f == 0)
#pragma unroll
        for (int i = 0; i < NPT; i++) {
            int n = nodeBase + gq * NPT + i;
            if (n < NN) { g_as[n] = ps[i]; g_ad[n] = pd[i]; }
        }
}

// ---- persistent warp-per-dst softmax + aggregation (R8 inner loop) ----------
__global__ void k_agg64(const float* __restrict__ bias, float* __restrict__ out) {
    __shared__ int2 ssw[8][64];      // (src, weight) staged per warp
    int wl = threadIdx.x >> 5;
    int lane = threadIdx.x & 31;
    int warp0 = (blockIdx.x << 3) + wl;
    int stride = gridDim.x << 3;

    for (int node = warp0; node < NN; node += stride) {
        int beg = g_off[node], end = g_off[node + 1];
        float adn = g_ad[node];

        int s0 = 0, s1 = 0;
        float e0 = -1e30f, e1 = -1e30f;
        int j0 = beg + lane, j1 = beg + 32 + lane;
        if (j0 < end) { s0 = g_esrc[j0]; float t = g_as[s0] + adn; e0 = t > 0.f ? t : 0.2f * t; }
        if (j1 < end) { s1 = g_esrc[j1]; float t = g_as[s1] + adn; e1 = t > 0.f ? t : 0.2f * t; }
        float mloc = fmaxf(e0, e1);
        for (int j = beg + 64 + lane; j < end; j += 32) {   // rare tail
            int s = g_esrc[j]; float t = g_as[s] + adn; t = t > 0.f ? t : 0.2f * t;
            mloc = fmaxf(mloc, t);
        }
        float m = funkey(__reduce_max_sync(0xFFFFFFFFu, fkey(mloc)));

        float w0 = (j0 < end) ? __expf(e0 - m) : 0.f;
        float w1 = (j1 < end) ? __expf(e1 - m) : 0.f;
        float den = w0 + w1;
        for (int j = beg + 64 + lane; j < end; j += 32) {
            int s = g_esrc[j]; float t = g_as[s] + adn; t = t > 0.f ? t : 0.2f * t;
            den += __expf(t - m);
        }
#pragma unroll
        for (int o = 16; o; o >>= 1) den += __shfl_xor_sync(0xFFFFFFFFu, den, o);
        float inv = 1.f / den;
        w0 *= inv; w1 *= inv;

        if (j0 < end) ssw[wl][lane]      = make_int2(s0, __float_as_int(w0));
        if (j1 < end) ssw[wl][32 + lane] = make_int2(s1, __float_as_int(w1));
        __syncwarp();

        unsigned long long acc = 0ull;   // feats 2lane, 2lane+1
        int dc = end - beg; if (dc > 64) dc = 64;
#pragma unroll 4
        for (int jj = 0; jj < dc; jj++) {
            int2 p = ssw[wl][jj];
            unsigned long long w2 = packf2(__int_as_float(p.y));
            const unsigned long long* row = (const unsigned long long*)(g_hf + (long long)p.x * 64);
            ffma2(acc, row[lane], w2);
        }
        for (int j = beg + 64; j < end; j++) {   // rare tail (uniform)
            int s = g_esrc[j];
            float t = g_as[s] + adn; t = t > 0.f ? t : 0.2f * t;
            unsigned long long w2 = packf2(__expf(t - m) * inv);
            const unsigned long long* row = (const unsigned long long*)(g_hf + (long long)s * 64);
            ffma2(acc, row[lane], w2);
        }

        float2 a = unpackf2(acc);
        float2 bb = ((const float2*)bias)[lane];
        float2 r;
        r.x = fmaxf(a.x + bb.x, 0.f);
        r.y = fmaxf(a.y + bb.y, 0.f);
        ((float2*)out)[node * 32 + lane] = r;
        __syncwarp();                 // protect ssw reuse next iteration
    }
}

// persistent layer-3 agg (F=8): quarter-warp per edge + mean-pool -------------
__global__ void k_agg8(const float* __restrict__ bias, const void* batch) {
    __shared__ int2 ssw[8][64];
    int wl = threadIdx.x >> 5;
    int lane = threadIdx.x & 31;
    int warp0 = (blockIdx.x << 3) + wl;
    int stride = gridDim.x << 3;
    int is64 = g_is64;

    for (int node = warp0; node < NN; node += stride) {
        int beg = g_off[node], end = g_off[node + 1];
        float adn = g_ad[node];

        int s0 = 0, s1 = 0;
        float e0 = -1e30f, e1 = -1e30f;
        int j0 = beg + lane, j1 = beg + 32 + lane;
        if (j0 < end) { s0 = g_esrc[j0]; float t = g_as[s0] + adn; e0 = t > 0.f ? t : 0.2f * t; }
        if (j1 < end) { s1 = g_esrc[j1]; float t = g_as[s1] + adn; e1 = t > 0.f ? t : 0.2f * t; }
        float mloc = fmaxf(e0, e1);
        for (int j = beg + 64 + lane; j < end; j += 32) {
            int s = g_esrc[j]; float t = g_as[s] + adn; t = t > 0.f ? t : 0.2f * t;
            mloc = fmaxf(mloc, t);
        }
        float m = funkey(__reduce_max_sync(0xFFFFFFFFu, fkey(mloc)));

        float w0 = (j0 < end) ? __expf(e0 - m) : 0.f;
        float w1 = (j1 < end) ? __expf(e1 - m) : 0.f;
        float den = w0 + w1;
        for (int j = beg + 64 + lane; j < end; j += 32) {
            int s = g_esrc[j]; float t = g_as[s] + adn; t = t > 0.f ? t : 0.2f * t;
            den += __expf(t - m);
        }
#pragma unroll
        for (int o = 16; o; o >>= 1) den += __shfl_xor_sync(0xFFFFFFFFu, den, o);
        float inv = 1.f / den;
        w0 *= inv; w1 *= inv;

        int dc = end - beg; if (dc > 64) dc = 64;
        int dpad = (dc + 7) & ~7;
        if (dpad > 64) dpad = 64;
        if (j0 < end) ssw[wl][lane]      = make_int2(s0, __float_as_int(w0));
        if (j1 < end) ssw[wl][32 + lane] = make_int2(s1, __float_as_int(w1));
        if (lane < 8 && dc + lane < dpad) ssw[wl][dc + lane] = make_int2(0, 0);
        __syncwarp();

        int g = lane >> 2, sub = lane & 3;
        unsigned long long acc = 0ull;   // feats 2sub, 2sub+1
        for (int jj = g; jj < dpad; jj += 8) {
            int2 p = ssw[wl][jj];
            unsigned long long w2 = packf2(__int_as_float(p.y));
            unsigned long long v = ((const unsigned long long*)(g_lin3 + (long long)p.x * CC))[sub];
            ffma2(acc, v, w2);
        }
        for (int j = beg + 64 + g; j < end; j += 8) {  // rare tail
            int s = g_esrc[j];
            float t = g_as[s] + adn; t = t > 0.f ? t : 0.2f * t;
            unsigned long long w2 = packf2(__expf(t - m) * inv);
            unsigned long long v = ((const unsigned long long*)(g_lin3 + (long long)s * CC))[sub];
            ffma2(acc, v, w2);
        }

        float2 a = unpackf2(acc);
#pragma unroll
        for (int o = 4; o <= 16; o <<= 1) {
            a.x += __shfl_xor_sync(0xFFFFFFFFu, a.x, o);
            a.y += __shfl_xor_sync(0xFFFFFFFFu, a.y, o);
        }

        int b = ldid(batch, node, is64);
        float* pool = (float*)&g_ints[OFF_POOL];
        if (lane < 4) {
            float2 bb = ((const float2*)bias)[lane];
            atomicAdd(&pool[b * CC + 2 * lane],     fmaxf(a.x + bb.x, 0.f));
            atomicAdd(&pool[b * CC + 2 * lane + 1], fmaxf(a.y + bb.y, 0.f));
        }
        if (lane == 0) atomicAdd(&g_ints[OFF_CNT + b], 1);
        __syncwarp();
    }
}

// ---------------- final mean + sigmoid ---------------------------------------
__global__ void k_fin(float* __restrict__ out) {
    int i = blockIdx.x * blockDim.x + threadIdx.x;
    if (i >= GG * CC) return;
    int g = i / CC;
    float c = fmaxf((float)g_ints[OFF_CNT + g], 1.f);
    float v = ((float*)&g_ints[OFF_POOL])[i] / c;
    out[i] = 1.f / (1.f + __expf(-v));
}

// -----------------------------------------------------------------------------
extern "C" void kernel_launch(void* const* d_in, const int* in_sizes, int n_in,
                              void* d_out, int out_size) {
    const float* x     = (const float*)d_in[0];
    const void*  ei    = d_in[1];
    const void*  batch = d_in[3];
    const float* W1  = (const float*)d_in[4];
    const float* a1s = (const float*)d_in[5];
    const float* a1d = (const float*)d_in[6];
    const float* b1  = (const float*)d_in[7];
    const float* W2  = (const float*)d_in[8];
    const float* a2s = (const float*)d_in[9];
    const float* a2d = (const float*)d_in[10];
    const float* b2  = (const float*)d_in[11];
    const float* W3  = (const float*)d_in[12];
    const float* a3s = (const float*)d_in[13];
    const float* a3d = (const float*)d_in[14];
    const float* b3  = (const float*)d_in[15];
    float* out = (float*)d_out;

    float* act;
    void* ints;
    cudaGetSymbolAddress((void**)&act, g_act);
    cudaGetSymbolAddress(&ints, g_ints);

    cudaMemsetAsync(ints, 0, INTS_TOTAL * sizeof(int), 0);

    // CSR build
    k_front<<<G1BLK + HBLK, 256>>>(x, W1, a1s, a1d, ei);
    k_scan<<<NBLK, 1024>>>();
    k_scatter<<<HBLK, 256>>>(ei);

    // launch 3 (ncu-profiled): layer-1 aggregation (persistent grid)
    k_agg64<<<AGGBLK, 256>>>(b1, act);

    // Layer 2: 64 -> 64
    k_gemm64<<<(NN + 31) / 32, 128>>>(act, W2, a2s, a2d);
    k_agg64<<<AGGBLK, 256>>>(b2, act);

    // Layer 3: 64 -> 8
    k_gemm3<<<(NN + 31) / 32, 64>>>(act, W3, a3s, a3d);
    k_agg8<<<AGGBLK, 256>>>(b3, batch);

    // mean + sigmoid
    k_fin<<<2, 256>>>(out);
}